// round 2
// baseline (speedup 1.0000x reference)
#include <cuda_runtime.h>
#include <cstdint>

// ============================================================================
// ESF_78391743086936 — fused global<->local attention block, algebraically
// restructured:
//   u      = global @ (Wq Wk^T) + Wk bq                      (drives softmax)
//   s2     = (local . u) / 16 ; a2 = softmax_k(s2)
//   pooled = sum_k a2[k] local[k]
//   out    = relu(pooled @ W_l + global @ W_g + c) + lf_mean + global
// with W_l = Wv Wf[:H], W_g = S_w * Wv Wf[H:], c = folded biases,
//      lf_mean = sum_k w_dr[k] local[k] + b_dr, S_w = sum w_dr.
// (bk cancels in softmax; lq/gk/lk/lv/gv never materialize.)
// GEMMs run on tensor cores via mma.sync m16n8k8 TF32 (rna-rounded).
// ============================================================================

constexpr int F  = 512;
constexpr int H  = 256;
constexpr int NL = 12;
constexpr int MAXB = 16384;

// ---- device scratch (allocation-free rule: __device__ globals) ----
__device__ uint32_t g_W1[F * 1024];           // tf32 [k=512][n=1024]: cols 0:512 = W_u, 512:1024 = W_g
__device__ uint32_t g_Wl[F * F];              // tf32 [k=512][n=512]  : W_l
__device__ float    g_bias1[1024];            // [b_u | c]
__device__ float    g_U[(size_t)MAXB * 1024]; // GEMM1 out: [u | global@W_g + c]
__device__ float    g_pooled[(size_t)MAXB * F];
__device__ float    g_resid[(size_t)MAXB * F]; // lf_mean + b_dr + global

__device__ __forceinline__ uint32_t f2tf(float x) {
    uint32_t u;
    asm("cvt.rna.tf32.f32 %0, %1;" : "=r"(u) : "f"(x));
    return u;
}

__device__ __forceinline__ void mma_tf32(float* d, const uint32_t* a, const uint32_t* b) {
    asm volatile(
        "mma.sync.aligned.m16n8k8.row.col.f32.tf32.tf32.f32 "
        "{%0,%1,%2,%3}, {%4,%5,%6,%7}, {%8,%9}, {%0,%1,%2,%3};\n"
        : "+f"(d[0]), "+f"(d[1]), "+f"(d[2]), "+f"(d[3])
        : "r"(a[0]), "r"(a[1]), "r"(a[2]), "r"(a[3]), "r"(b[0]), "r"(b[1]));
}

// ============================================================================
// K0a: fused bias vectors.
//   bias1[f]      = b_u[f] = sum_h Wk[f,h] bq[h]                     (f < 512)
//   bias1[512+f'] = bf[f'] + sum_h bv[h] Wf[h,f']
//                 + sum_h (S_w*bv[h] + b_dr) Wf[256+h,f']            (c vector)
// ============================================================================
__global__ void k0_bias_kernel(const float* __restrict__ Wk, const float* __restrict__ bq,
                               const float* __restrict__ bv, const float* __restrict__ wdr,
                               const float* __restrict__ bdr_p, const float* __restrict__ Wf,
                               const float* __restrict__ bf)
{
    int tid = blockIdx.x * blockDim.x + threadIdx.x;
    float Sw = 0.f;
#pragma unroll
    for (int k = 0; k < NL; k++) Sw += wdr[k];
    float bdr = bdr_p[0];
    if (tid < F) {
        float s = 0.f;
        for (int h = 0; h < H; h++) s += Wk[tid * H + h] * bq[h];
        g_bias1[tid] = s;
    } else if (tid < 2 * F) {
        int f = tid - F;
        float s = bf[f];
        for (int h = 0; h < H; h++) {
            s += bv[h] * Wf[h * F + f];
            s += (Sw * bv[h] + bdr) * Wf[(H + h) * F + f];
        }
        g_bias1[F + f] = s;
    }
}

// ============================================================================
// K0b: fused weight matrices (512x512, K=256 each), stored as TF32.
//   z=0: W_u[f,f'] = sum_h Wq[f,h] Wk[f',h]         -> g_W1 cols [0,512)
//   z=1: W_l[f,f'] = sum_h Wv[f,h] Wf[h,f']         -> g_Wl
//   z=2: W_g[f,f'] = S_w * sum_h Wv[f,h] Wf[H+h,f'] -> g_W1 cols [512,1024)
// ============================================================================
__global__ void k0_mats_kernel(const float* __restrict__ Wq, const float* __restrict__ Wk,
                               const float* __restrict__ Wv, const float* __restrict__ Wf,
                               const float* __restrict__ wdr)
{
    int z  = blockIdx.z;
    int tx = threadIdx.x, ty = threadIdx.y;
    int row = blockIdx.y * 16 + ty;   // f
    int col = blockIdx.x * 16 + tx;   // f'
    __shared__ float As[16][16];
    __shared__ float Bs[16][17];
    float acc = 0.f;
    const float* A = (z == 0) ? Wq : Wv;
    for (int hh = 0; hh < H; hh += 16) {
        As[ty][tx] = A[row * H + hh + tx];
        if (z == 0) {
            Bs[ty][tx] = Wk[(blockIdx.x * 16 + ty) * H + hh + tx]; // Wk[f', h]
        } else {
            int hofs = (z == 2) ? H : 0;
            Bs[ty][tx] = Wf[(hofs + hh + ty) * F + col];           // Wf[h, f']
        }
        __syncthreads();
        if (z == 0) {
#pragma unroll
            for (int k = 0; k < 16; k++) acc += As[ty][k] * Bs[tx][k];
        } else {
#pragma unroll
            for (int k = 0; k < 16; k++) acc += As[ty][k] * Bs[k][tx];
        }
        __syncthreads();
    }
    if (z == 2) {
        float Sw = 0.f;
#pragma unroll
        for (int k = 0; k < NL; k++) Sw += wdr[k];
        acc *= Sw;
    }
    uint32_t t = f2tf(acc);
    if (z == 1) g_Wl[row * F + col] = t;
    else        g_W1[row * 1024 + ((z == 2) ? F : 0) + col] = t;
}

// ============================================================================
// TF32 GEMM: C[M,N] = A[M,512] @ W[512,N] (+ epilogue).
// BM=128, BN=128, BK=32, 256 threads (8 warps, 2x4 warp grid, 64x32 per warp).
// MODE 0: A=global, W=g_W1 (N=1024), C=g_U, += g_bias1.
// MODE 1: A=g_pooled, W=g_Wl (N=512), out = relu(acc + g_U[:,512+n]) + g_resid.
// ============================================================================
template<int MODE>
__global__ void __launch_bounds__(256, 2)
gemm_tf32_kernel(const float* __restrict__ Ain, float* __restrict__ Cout)
{
    constexpr int N = (MODE == 0) ? 1024 : 512;
    const float*    __restrict__ A  = (MODE == 0) ? Ain : g_pooled;
    const uint32_t* __restrict__ Wt = (MODE == 0) ? g_W1 : g_Wl;

    __shared__ uint32_t smA[128 * 36];   // [m][k], row stride 36 (pad 4)
    __shared__ uint32_t smB[32 * 132];   // [k][n], row stride 132 (pad 4)

    const int tid  = threadIdx.x;
    const int warp = tid >> 5, lane = tid & 31;
    const int wm = (warp & 1) * 64, wn = (warp >> 1) * 32;
    const int bm = blockIdx.y * 128, bn = blockIdx.x * 128;

    float acc[4][4][4];
#pragma unroll
    for (int i = 0; i < 4; i++)
#pragma unroll
        for (int j = 0; j < 4; j++)
#pragma unroll
            for (int v = 0; v < 4; v++) acc[i][j][v] = 0.f;

    const int ra = tid >> 3;            // 0..31
    const int ca = (tid & 7) << 2;      // 0,4,...,28
    const int rb = tid >> 5;            // 0..7
    const int cb = (tid & 31) << 2;     // 0..124

    for (int kt = 0; kt < 512; kt += 32) {
        // stage A (fp32 -> tf32)
#pragma unroll
        for (int i = 0; i < 4; i++) {
            const float4 v = *reinterpret_cast<const float4*>(
                &A[(size_t)(bm + ra + 32 * i) * 512 + kt + ca]);
            uint4 u;
            u.x = f2tf(v.x); u.y = f2tf(v.y); u.z = f2tf(v.z); u.w = f2tf(v.w);
            *reinterpret_cast<uint4*>(&smA[(ra + 32 * i) * 36 + ca]) = u;
        }
        // stage B (already tf32)
#pragma unroll
        for (int i = 0; i < 4; i++) {
            uint4 v = *reinterpret_cast<const uint4*>(
                &Wt[(size_t)(kt + rb + 8 * i) * N + bn + cb]);
            *reinterpret_cast<uint4*>(&smB[(rb + 8 * i) * 132 + cb]) = v;
        }
        __syncthreads();

#pragma unroll
        for (int kk = 0; kk < 32; kk += 8) {
            uint32_t af[4][4], bfr[4][2];
#pragma unroll
            for (int mf = 0; mf < 4; mf++) {
                int r0 = wm + mf * 16 + (lane >> 2);
                int c0 = kk + (lane & 3);
                af[mf][0] = smA[r0 * 36 + c0];
                af[mf][1] = smA[(r0 + 8) * 36 + c0];
                af[mf][2] = smA[r0 * 36 + c0 + 4];
                af[mf][3] = smA[(r0 + 8) * 36 + c0 + 4];
            }
#pragma unroll
            for (int nf = 0; nf < 4; nf++) {
                int n0 = wn + nf * 8 + (lane >> 2);
                int k0 = kk + (lane & 3);
                bfr[nf][0] = smB[k0 * 132 + n0];
                bfr[nf][1] = smB[(k0 + 4) * 132 + n0];
            }
#pragma unroll
            for (int mf = 0; mf < 4; mf++)
#pragma unroll
                for (int nf = 0; nf < 4; nf++)
                    mma_tf32(acc[mf][nf], af[mf], bfr[nf]);
        }
        __syncthreads();
    }

    // epilogue: d0:(r,c) d1:(r,c+1) d2:(r+8,c) d3:(r+8,c+1)
#pragma unroll
    for (int mf = 0; mf < 4; mf++) {
        int r0 = bm + wm + mf * 16 + (lane >> 2);
#pragma unroll
        for (int nf = 0; nf < 4; nf++) {
            int c0 = bn + wn + nf * 8 + ((lane & 3) << 1);
            if (MODE == 0) {
                float b0 = g_bias1[c0], b1 = g_bias1[c0 + 1];
                g_U[(size_t)r0 * 1024 + c0]           = acc[mf][nf][0] + b0;
                g_U[(size_t)r0 * 1024 + c0 + 1]       = acc[mf][nf][1] + b1;
                g_U[(size_t)(r0 + 8) * 1024 + c0]     = acc[mf][nf][2] + b0;
                g_U[(size_t)(r0 + 8) * 1024 + c0 + 1] = acc[mf][nf][3] + b1;
            } else {
#pragma unroll
                for (int half = 0; half < 2; half++) {
                    int r = r0 + 8 * half;
                    float z0 = acc[mf][nf][2 * half + 0] + g_U[(size_t)r * 1024 + 512 + c0];
                    float z1 = acc[mf][nf][2 * half + 1] + g_U[(size_t)r * 1024 + 512 + c0 + 1];
                    Cout[(size_t)r * 512 + c0]     = fmaxf(z0, 0.f) + g_resid[(size_t)r * 512 + c0];
                    Cout[(size_t)r * 512 + c0 + 1] = fmaxf(z1, 0.f) + g_resid[(size_t)r * 512 + c0 + 1];
                }
            }
        }
    }
}

// ============================================================================
// K2: per-row attention over the 12 local tokens (streaming, HBM-bound).
// One block per b, 128 threads, 4 floats per thread. Computes s2 -> softmax
// -> pooled, plus lf_mean residual (lf_mean + b_dr + global).
// ============================================================================
__global__ void k2_attn_kernel(const float* __restrict__ gfeat,
                               const float* __restrict__ lfeat,
                               const float* __restrict__ wdr,
                               const float* __restrict__ bdr_p)
{
    const int b = blockIdx.x;
    const int t = threadIdx.x;     // 128
    const int f0 = t * 4;
    const float* lb = lfeat + (size_t)b * NL * F;

    float4 u4 = *reinterpret_cast<const float4*>(&g_U[(size_t)b * 1024 + f0]);

    float4 loc[NL];
    float part[NL];
#pragma unroll
    for (int k = 0; k < NL; k++) {
        loc[k] = *reinterpret_cast<const float4*>(&lb[k * F + f0]);
        part[k] = loc[k].x * u4.x + loc[k].y * u4.y + loc[k].z * u4.z + loc[k].w * u4.w;
    }
#pragma unroll
    for (int k = 0; k < NL; k++) {
#pragma unroll
        for (int o = 16; o > 0; o >>= 1)
            part[k] += __shfl_xor_sync(0xffffffffu, part[k], o);
    }
    __shared__ float red[4][NL];
    const int lane = t & 31, w = t >> 5;
    if (lane == 0) {
#pragma unroll
        for (int k = 0; k < NL; k++) red[w][k] = part[k];
    }
    __syncthreads();

    float a2[NL];
    float m = -1e30f;
#pragma unroll
    for (int k = 0; k < NL; k++) {
        a2[k] = (red[0][k] + red[1][k] + red[2][k] + red[3][k]) * 0.0625f; // 1/sqrt(256)
        m = fmaxf(m, a2[k]);
    }
    float s = 0.f;
#pragma unroll
    for (int k = 0; k < NL; k++) { a2[k] = __expf(a2[k] - m); s += a2[k]; }
    const float inv = 1.f / s;

    float4 pool = make_float4(0.f, 0.f, 0.f, 0.f);
    float4 lfm  = make_float4(0.f, 0.f, 0.f, 0.f);
#pragma unroll
    for (int k = 0; k < NL; k++) {
        float a  = a2[k] * inv;
        float wd = wdr[k];
        pool.x += a * loc[k].x;  pool.y += a * loc[k].y;
        pool.z += a * loc[k].z;  pool.w += a * loc[k].w;
        lfm.x  += wd * loc[k].x; lfm.y  += wd * loc[k].y;
        lfm.z  += wd * loc[k].z; lfm.w  += wd * loc[k].w;
    }
    float4 g4 = *reinterpret_cast<const float4*>(&gfeat[(size_t)b * F + f0]);
    const float bdr = bdr_p[0];
    float4 rez = make_float4(lfm.x + bdr + g4.x, lfm.y + bdr + g4.y,
                             lfm.z + bdr + g4.z, lfm.w + bdr + g4.w);
    *reinterpret_cast<float4*>(&g_pooled[(size_t)b * F + f0]) = pool;
    *reinterpret_cast<float4*>(&g_resid [(size_t)b * F + f0]) = rez;
}

// ============================================================================
extern "C" void kernel_launch(void* const* d_in, const int* in_sizes, int n_in,
                              void* d_out, int out_size)
{
    const float* gfeat = (const float*)d_in[0];
    const float* lfeat = (const float*)d_in[1];
    const float* Wq    = (const float*)d_in[2];
    const float* bq    = (const float*)d_in[3];
    const float* Wk    = (const float*)d_in[4];
    // d_in[5] (bk) is mathematically irrelevant: it shifts all 12 softmax
    // logits equally and cancels.
    const float* Wv    = (const float*)d_in[6];
    const float* bv    = (const float*)d_in[7];
    const float* wdr   = (const float*)d_in[8];
    const float* bdr   = (const float*)d_in[9];
    const float* Wf    = (const float*)d_in[10];
    const float* bf    = (const float*)d_in[11];
    float* out = (float*)d_out;

    const int B = in_sizes[0] / F;   // 16384

    k0_bias_kernel<<<4, 256>>>(Wk, bq, bv, wdr, bdr, Wf, bf);
    k0_mats_kernel<<<dim3(F / 16, F / 16, 3), dim3(16, 16)>>>(Wq, Wk, Wv, Wf, wdr);
    gemm_tf32_kernel<0><<<dim3(1024 / 128, B / 128), 256>>>(gfeat, nullptr);
    k2_attn_kernel<<<B, 128>>>(gfeat, lfeat, wdr, bdr);
    gemm_tf32_kernel<1><<<dim3(512 / 128, B / 128), 256>>>(nullptr, out);
}